// round 9
// baseline (speedup 1.0000x reference)
#include <cuda_runtime.h>
#include <cstdint>
#include <math_constants.h>

#define N_MAX 65536
#define M_IND 1024
#define KNN 16
#define BUFCAP 128
#define SU_NB 32
#define SU_BLOCKS (SU_NB * (SU_NB + 1) / 2)   // 528

// Scratch (static device globals — no allocation allowed)
__device__ unsigned g_idx[N_MAX * KNN];
__device__ float    g_Su[M_IND * M_IND];

// ---------------------------------------------------------------------------
// Kernel 1: Su = Lu Lu^T. 32x32 tiles, 528 triangular blocks, 256 thr, 2x2.
// ---------------------------------------------------------------------------
__global__ void su_kernel(const float* __restrict__ raw) {
    __shared__ float At[32][33];
    __shared__ float Bt[32][33];
    int s = blockIdx.x;
    int bi = (int)((__fsqrt_rn(8.0f * (float)s + 1.0f) - 1.0f) * 0.5f);
    while ((bi + 1) * (bi + 2) / 2 <= s) bi++;
    while (bi * (bi + 1) / 2 > s) bi--;
    int bj = s - bi * (bi + 1) / 2;          // bj <= bi

    int tid = threadIdx.x;
    int tx = tid & 15, ty = tid >> 4;
    int lr = tid >> 3;                       // 0..31 row in tile
    int lc = (tid & 7) << 2;                 // k col group of 4
    int rA = bi * 32, rB = bj * 32;
    int nk = (bj + 1) * 32;                  // k <= min(i,j); rest is 0

    float acc00 = 0.f, acc01 = 0.f, acc10 = 0.f, acc11 = 0.f;
    for (int kc = 0; kc < nk; kc += 32) {
        int ga = rA + lr;
        float4 va = *(const float4*)(raw + (size_t)ga * M_IND + kc + lc);
        int gb = rB + lr;
        float4 vb = *(const float4*)(raw + (size_t)gb * M_IND + kc + lc);
        float a4[4] = {va.x, va.y, va.z, va.w};
        float b4[4] = {vb.x, vb.y, vb.z, vb.w};
#pragma unroll
        for (int u = 0; u < 4; u++) {
            int gc = kc + lc + u;
            float x = a4[u];
            At[lc + u][lr] = (gc < ga) ? x : ((gc == ga) ? expf(x) : 0.0f);
            float y = b4[u];
            Bt[lc + u][lr] = (gc < gb) ? y : ((gc == gb) ? expf(y) : 0.0f);
        }
        __syncthreads();
#pragma unroll
        for (int kk = 0; kk < 32; kk++) {
            float a0 = At[kk][ty * 2], a1 = At[kk][ty * 2 + 1];
            float b0 = Bt[kk][tx * 2], b1 = Bt[kk][tx * 2 + 1];
            acc00 = fmaf(a0, b0, acc00);
            acc01 = fmaf(a0, b1, acc01);
            acc10 = fmaf(a1, b0, acc10);
            acc11 = fmaf(a1, b1, acc11);
        }
        __syncthreads();
    }
    int gi0 = rA + ty * 2, gj0 = rB + tx * 2;
    g_Su[(size_t)gi0 * M_IND + gj0]           = acc00;
    g_Su[(size_t)gi0 * M_IND + gj0 + 1]       = acc01;
    g_Su[(size_t)(gi0 + 1) * M_IND + gj0]     = acc10;
    g_Su[(size_t)(gi0 + 1) * M_IND + gj0 + 1] = acc11;
    g_Su[(size_t)gj0 * M_IND + gi0]           = acc00;
    g_Su[(size_t)(gj0 + 1) * M_IND + gi0]     = acc01;
    g_Su[(size_t)gj0 * M_IND + gi0 + 1]       = acc10;
    g_Su[(size_t)(gj0 + 1) * M_IND + gi0 + 1] = acc11;
}

// ---------------------------------------------------------------------------
// Kernel 2: exact 16-NN, TWO threads per point (each scans a 512-half of Z).
// ---------------------------------------------------------------------------
__global__ void topk_kernel(const float* __restrict__ X,
                            const float* __restrict__ Z, int N) {
    __shared__ float4 zs[M_IND];
    for (int t = threadIdx.x; t < M_IND; t += blockDim.x) {
        float a = Z[3 * t], b = Z[3 * t + 1], c = Z[3 * t + 2];
        zs[t] = make_float4(a, b, c, fmaf(a, a, fmaf(b, b, c * c)));
    }
    __syncthreads();
    const unsigned FULL = 0xFFFFFFFFu;
    int g = blockIdx.x * blockDim.x + threadIdx.x;   // 2N threads exactly
    int p = g >> 1;
    int sub = g & 1;
    int lane = threadIdx.x & 31;
    unsigned pmask = 3u << (lane & ~1);              // pair mask
    int h0 = sub << 9;                               // own half start

    float x0 = X[3 * p], x1 = X[3 * p + 1], x2 = X[3 * p + 2];
    float xs = fmaf(x0, x0, fmaf(x1, x1, x2 * x2));
    float n0 = -2.0f * x0, n1 = -2.0f * x1, n2 = -2.0f * x2;

#define DIST(Zv) fmaxf(fmaf(n0, (Zv).x, fmaf(n1, (Zv).y, fmaf(n2, (Zv).z, xs + (Zv).w))), 0.0f)

    // ---- P1: 64 samples of own half (stride 8), 4-way interleaved bubble ---
    float ks[KNN];
#pragma unroll
    for (int s = 0; s < KNN; s++) ks[s] = CUDART_INF_F;
    for (int i = h0; i < h0 + 512; i += 32) {
        float4 z0 = zs[i], z1 = zs[i + 8], z2v = zs[i + 16], z3 = zs[i + 24];
        float t0 = DIST(z0), t1 = DIST(z1), t2 = DIST(z2v), t3 = DIST(z3);
#pragma unroll
        for (int s = 0; s < KNN; s++) {
            float a = ks[s];
            float m0 = fminf(a, t0);  t0 = fmaxf(a, t0);
            float m1 = fminf(m0, t1); t1 = fmaxf(m0, t1);
            float m2 = fminf(m1, t2); t2 = fmaxf(m1, t2);
            float m3 = fminf(m2, t3); t3 = fmaxf(m2, t3);
            ks[s] = m3;
        }
    }
    float T0 = fminf(ks[KNN - 1], __shfl_xor_sync(FULL, ks[KNN - 1], 1));

    // ---- P2: predicated u16 buffering over own half ----
    unsigned short buf[BUFCAP];
    int c = 0;
    for (int i = h0; i < h0 + 512; i += 8) {
        int t[8];
#pragma unroll
        for (int u = 0; u < 8; u++) {
            float4 z = zs[i + u];
            t[u] = DIST(z) <= T0;
        }
        int s01 = t[0] + t[1], s23 = t[2] + t[3];
        int s45 = t[4] + t[5], s67 = t[6] + t[7];
        int s03 = s01 + s23;
        int pre[8];
        pre[0] = 0;         pre[1] = t[0];
        pre[2] = s01;       pre[3] = s01 + t[2];
        pre[4] = s03;       pre[5] = s03 + t[4];
        pre[6] = s03 + s45; pre[7] = s03 + s45 + t[6];
#pragma unroll
        for (int u = 0; u < 8; u++) {
            int w = c + pre[u];
            w = w < BUFCAP ? w : BUFCAP - 1;
            if (t[u]) buf[w] = (unsigned short)(i + u);
        }
        c += s03 + s45 + s67;
    }
    int ovf = (c > BUFCAP);
    int fb = ovf | __shfl_xor_sync(FULL, ovf, 1);    // pair-uniform

    unsigned base = (unsigned)p * KNN;
    if (!fb) {
        // ---- P3: bubble own candidates -> local sorted top-16 values ----
        float ks3[KNN];
#pragma unroll
        for (int s = 0; s < KNN; s++) ks3[s] = CUDART_INF_F;
        int c2 = c & ~1;
        for (int j = 0; j < c2; j += 2) {
            float4 za = zs[buf[j]], zb = zs[buf[j + 1]];
            float ta = DIST(za), tb = DIST(zb);
#pragma unroll
            for (int s = 0; s < KNN; s++) {
                float a = ks3[s];
                float m0 = fminf(a, ta);  ta = fmaxf(a, ta);
                float m1 = fminf(m0, tb); tb = fmaxf(m0, tb);
                ks3[s] = m1;
            }
        }
        if (c & 1) {
            float4 za = zs[buf[c - 1]];
            float ta = DIST(za);
#pragma unroll
            for (int s = 0; s < KNN; s++) {
                float a = ks3[s];
                ks3[s] = fminf(a, ta); ta = fmaxf(a, ta);
            }
        }
        // ---- merge-path 16th statistic of own+partner sorted lists ----
        float Bv[KNN];
#pragma unroll
        for (int s = 0; s < KNN; s++)
            Bv[s] = __shfl_xor_sync(pmask, ks3[s], 1);
        float Tstar = fminf(Bv[15], ks3[15]);        // i=0 and i=16
#pragma unroll
        for (int i = 1; i < 16; i++)
            Tstar = fminf(Tstar, fmaxf(ks3[i - 1], Bv[15 - i]));

        // ---- P4: counts, exchange, emission ----
        int nLess = 0, nTie = 0;
        for (int j = 0; j < c; j++) {
            float4 z = zs[buf[j]];
            float d = DIST(z);
            nLess += (d < Tstar);
            nTie  += (d == Tstar);
        }
        int nLessP = __shfl_xor_sync(pmask, nLess, 1);
        int nTieP  = __shfl_xor_sync(pmask, nTie, 1);
        int r = KNN - nLess - nLessP;                // tie budget (>= 0)
        int strictOff, tieOff, tieBudget;
        if (sub == 0) {
            strictOff = 0;
            tieOff    = nLess + nLessP;
            tieBudget = r < nTie ? r : nTie;
        } else {
            int tieUseA = r < nTieP ? r : nTieP;     // half-0 ties go first
            strictOff = nLessP;
            tieOff    = nLess + nLessP + tieUseA;
            tieBudget = (r - tieUseA) < nTie ? (r - tieUseA) : nTie;
        }
        int cnt = 0;
        for (int j = 0; j < c; j++) {
            int i = buf[j];
            float4 z = zs[i];
            float d = DIST(z);
            bool em = (d < Tstar);
            if (em) g_idx[base + strictOff + cnt] = (unsigned)i;
            cnt += em;
        }
        int cnt2 = 0;
        for (int j = 0; j < c; j++) {
            int i = buf[j];
            float4 z = zs[i];
            float d = DIST(z);
            bool em = (d == Tstar) & (cnt2 < tieBudget);
            if (em) g_idx[base + tieOff + cnt2] = (unsigned)i;
            cnt2 += em;
        }
    } else if (sub == 0) {
        // Fallback: full exact u64 replace-max over all 1024 (pathological)
        unsigned long long ks2[KNN];
#pragma unroll
        for (int s = 0; s < KNN; s++)
            ks2[s] = 0xFFFFFFFF00000000ull | (unsigned)s;
        unsigned long long kmax2 = 0xFFFFFFFF0000000Full;
        for (int i = 0; i < M_IND; i++) {
            float4 z = zs[i];
            float dd = DIST(z);
            unsigned long long key =
                ((unsigned long long)__float_as_uint(dd) << 32) | (unsigned)i;
            if (key < kmax2) {
#pragma unroll
                for (int s = 0; s < KNN; s++) ks2[s] = (ks2[s] == kmax2) ? key : ks2[s];
                unsigned long long m = ks2[0];
#pragma unroll
                for (int s = 1; s < KNN; s++) m = max(m, ks2[s]);
                kmax2 = m;
            }
        }
#pragma unroll
        for (int s = 0; s < KNN; s++)
            g_idx[base + s] = (unsigned)(ks2[s] & 0xFFFFFFFFu);
    }
#undef DIST
}

// ---------------------------------------------------------------------------
// Kernel 3: half-warp per point, register fp32 Gauss-Jordan; symmetric cov.
// ---------------------------------------------------------------------------
__global__ void solve_kernel(const float* __restrict__ X,
                             const float* __restrict__ Z,
                             const float* __restrict__ mu,
                             float* __restrict__ out, int N) {
    const unsigned FULL = 0xFFFFFFFFu;
    int lane = threadIdx.x & 31;
    int half = lane >> 4;
    int l = lane & 15;
    int p = (blockIdx.x << 4) + ((threadIdx.x >> 5) << 1) + half;
    int pc = p < N ? p : N - 1;

    float x0 = X[3 * pc], x1 = X[3 * pc + 1], x2 = X[3 * pc + 2];
    float xs = fmaf(x0, x0, fmaf(x1, x1, x2 * x2));

    unsigned idxv = g_idx[(size_t)pc * KNN + l];
    float zx = Z[3 * idxv], zy = Z[3 * idxv + 1], zz = Z[3 * idxv + 2];
    float z2 = fmaf(zx, zx, fmaf(zy, zy, zz * zz));
    float d2r = fmaxf(xs + z2 - 2.0f * fmaf(x0, zx, fmaf(x1, zy, x2 * zz)), 0.0f);
    float muv = mu[idxv];

    float a[17];
    a[16] = expf(-0.5f * d2r);   // rhs = lKxz

#pragma unroll
    for (int i = 0; i < 16; i++) {
        float zxi = __shfl_sync(FULL, zx, i, 16);
        float zyi = __shfl_sync(FULL, zy, i, 16);
        float zzi = __shfl_sync(FULL, zz, i, 16);
        float dx = zxi - zx, dy = zyi - zy, dz = zzi - zz;
        float d2 = fmaf(dx, dx, fmaf(dy, dy, dz * dz));
        a[i] = (i == l) ? (1.0f + 2e-4f) : expf(-0.5f * d2);
    }

#pragma unroll
    for (int k = 0; k < 16; k++) {
        float piv = __shfl_sync(FULL, a[k], k, 16);
        float rp = 1.0f / piv;
        float f = (l == k) ? 0.0f : a[k] * rp;
#pragma unroll
        for (int cc = k + 1; cc <= 16; cc++) {
            float bc = __shfl_sync(FULL, a[cc], k, 16);
            a[cc] = fmaf(-f, bc, a[cc]);
        }
    }
    float diag = a[0];
#pragma unroll
    for (int cc = 1; cc < 16; cc++) if (l == cc) diag = a[cc];
    float Wv = a[16] / diag;

    // cov = 1 + Wv^2 (su_ll - (1+1e-4)) + 2 * sum_{i<l} Wi Wv (su_il - kv_il)
    float acc = 0.0f;
#pragma unroll
    for (int i = 0; i < 15; i++) {
        float Wi = __shfl_sync(FULL, Wv, i, 16);
        unsigned ia = __shfl_sync(FULL, idxv, i, 16);
        float zxi = __shfl_sync(FULL, zx, i, 16);
        float zyi = __shfl_sync(FULL, zy, i, 16);
        float zzi = __shfl_sync(FULL, zz, i, 16);
        bool keep = (i < l);
        const float* addr = keep ? (g_Su + (size_t)ia * M_IND + idxv) : g_Su;
        float su = __ldg(addr);
        float dx = zxi - zx, dy = zyi - zy, dz = zzi - zz;
        float d2 = fmaf(dx, dx, fmaf(dy, dy, dz * dz));
        float kv = expf(-0.5f * d2);
        float coef = keep ? 2.0f * Wi * Wv : 0.0f;
        acc = fmaf(coef, su - kv, acc);
    }
    {
        float su_ll = __ldg(g_Su + (size_t)idxv * M_IND + idxv);
        acc = fmaf(Wv * Wv, su_ll - 1.0001f, acc);
    }
    float mpart = Wv * muv;
#pragma unroll
    for (int o = 8; o > 0; o >>= 1) {
        acc   += __shfl_xor_sync(FULL, acc, o, 16);
        mpart += __shfl_xor_sync(FULL, mpart, o, 16);
    }
    if (l == 0 && p < N) {
        out[p] = mpart;                                // mean
        float cov = 1.0f + acc;
        out[N + p] = sqrtf(fmaxf(cov, 0.05f));         // std
    }
}

// ---------------------------------------------------------------------------
extern "C" void kernel_launch(void* const* d_in, const int* in_sizes, int n_in,
                              void* d_out, int out_size) {
    const float* X      = (const float*)d_in[0];
    const float* Z      = (const float*)d_in[1];
    const float* Lu_raw = (const float*)d_in[2];
    const float* mu     = (const float*)d_in[3];
    float* out = (float*)d_out;
    int N = in_sizes[0] / 3;

    topk_kernel<<<(2 * N + 127) / 128, 128>>>(X, Z, N);
    su_kernel<<<SU_BLOCKS, 256>>>(Lu_raw);
    solve_kernel<<<(N + 15) / 16, 256>>>(X, Z, mu, out, N);
}

// round 10
// speedup vs baseline: 2.1151x; 2.1151x over previous
#include <cuda_runtime.h>
#include <cstdint>
#include <math_constants.h>

#define N_MAX 65536
#define M_IND 1024
#define KNN 16
#define BUFCAP 128
#define SU_NB 32
#define SU_BLOCKS (SU_NB * (SU_NB + 1) / 2)   // 528

// Scratch (static device globals — no allocation allowed)
__device__ unsigned g_idx[N_MAX * KNN];
__device__ float    g_Su[M_IND * M_IND];

// ---------------------------------------------------------------------------
// Kernel 1: Su = Lu Lu^T. 32x32 tiles, 528 triangular blocks, 256 thr, 2x2.
// ---------------------------------------------------------------------------
__global__ void su_kernel(const float* __restrict__ raw) {
    __shared__ float At[32][33];
    __shared__ float Bt[32][33];
    int s = blockIdx.x;
    int bi = (int)((__fsqrt_rn(8.0f * (float)s + 1.0f) - 1.0f) * 0.5f);
    while ((bi + 1) * (bi + 2) / 2 <= s) bi++;
    while (bi * (bi + 1) / 2 > s) bi--;
    int bj = s - bi * (bi + 1) / 2;          // bj <= bi

    int tid = threadIdx.x;
    int tx = tid & 15, ty = tid >> 4;
    int lr = tid >> 3;                       // 0..31 row in tile
    int lc = (tid & 7) << 2;                 // k col group of 4
    int rA = bi * 32, rB = bj * 32;
    int nk = (bj + 1) * 32;                  // k <= min(i,j); rest is 0

    float acc00 = 0.f, acc01 = 0.f, acc10 = 0.f, acc11 = 0.f;
    for (int kc = 0; kc < nk; kc += 32) {
        int ga = rA + lr;
        float4 va = *(const float4*)(raw + (size_t)ga * M_IND + kc + lc);
        int gb = rB + lr;
        float4 vb = *(const float4*)(raw + (size_t)gb * M_IND + kc + lc);
        float a4[4] = {va.x, va.y, va.z, va.w};
        float b4[4] = {vb.x, vb.y, vb.z, vb.w};
#pragma unroll
        for (int u = 0; u < 4; u++) {
            int gc = kc + lc + u;
            float x = a4[u];
            At[lc + u][lr] = (gc < ga) ? x : ((gc == ga) ? expf(x) : 0.0f);
            float y = b4[u];
            Bt[lc + u][lr] = (gc < gb) ? y : ((gc == gb) ? expf(y) : 0.0f);
        }
        __syncthreads();
#pragma unroll
        for (int kk = 0; kk < 32; kk++) {
            float a0 = At[kk][ty * 2], a1 = At[kk][ty * 2 + 1];
            float b0 = Bt[kk][tx * 2], b1 = Bt[kk][tx * 2 + 1];
            acc00 = fmaf(a0, b0, acc00);
            acc01 = fmaf(a0, b1, acc01);
            acc10 = fmaf(a1, b0, acc10);
            acc11 = fmaf(a1, b1, acc11);
        }
        __syncthreads();
    }
    int gi0 = rA + ty * 2, gj0 = rB + tx * 2;
    g_Su[(size_t)gi0 * M_IND + gj0]           = acc00;
    g_Su[(size_t)gi0 * M_IND + gj0 + 1]       = acc01;
    g_Su[(size_t)(gi0 + 1) * M_IND + gj0]     = acc10;
    g_Su[(size_t)(gi0 + 1) * M_IND + gj0 + 1] = acc11;
    g_Su[(size_t)gj0 * M_IND + gi0]           = acc00;
    g_Su[(size_t)(gj0 + 1) * M_IND + gi0]     = acc01;
    g_Su[(size_t)gj0 * M_IND + gi0 + 1]       = acc10;
    g_Su[(size_t)(gj0 + 1) * M_IND + gi0 + 1] = acc11;
}

// ---------------------------------------------------------------------------
// Kernel 2: exact 16-NN, thread per point.
//  P1: full scan, 16 running group-mins (groups of 64) -> T0 = max of mins.
//      Valid: 16 distinct z's have d <= T0 => true 16th-smallest <= T0.
//  P2: predicated u16 buffering of {d <= T0} (expected c ~ 50).
//  P3: 2-way interleaved 16-deep bubble over candidates -> exact 16th T*.
//  P4: emit d < T*, then ties d == T* ascending index (stable tie-break).
// ---------------------------------------------------------------------------
__global__ void topk_kernel(const float* __restrict__ X,
                            const float* __restrict__ Z, int N) {
    __shared__ float4 zs[M_IND];
    for (int t = threadIdx.x; t < M_IND; t += blockDim.x) {
        float a = Z[3 * t], b = Z[3 * t + 1], c = Z[3 * t + 2];
        zs[t] = make_float4(a, b, c, fmaf(a, a, fmaf(b, b, c * c)));
    }
    __syncthreads();
    int p = blockIdx.x * blockDim.x + threadIdx.x;
    if (p >= N) return;
    float x0 = X[3 * p], x1 = X[3 * p + 1], x2 = X[3 * p + 2];
    float xs = fmaf(x0, x0, fmaf(x1, x1, x2 * x2));
    float n0 = -2.0f * x0, n1 = -2.0f * x1, n2 = -2.0f * x2;

#define DIST(Zv) fmaxf(fmaf(n0, (Zv).x, fmaf(n1, (Zv).y, fmaf(n2, (Zv).z, xs + (Zv).w))), 0.0f)

    // ---- P1: full scan, 16 interleaved group-min chains ----
    float mins[16];
#pragma unroll
    for (int g = 0; g < 16; g++) mins[g] = CUDART_INF_F;
#pragma unroll 2
    for (int jj = 0; jj < 64; jj++) {
#pragma unroll
        for (int g = 0; g < 16; g++) {
            float4 z = zs[(g << 6) + jj];
            mins[g] = fminf(mins[g], DIST(z));
        }
    }
    float T0 = mins[0];
#pragma unroll
    for (int g = 1; g < 16; g++) T0 = fmaxf(T0, mins[g]);

    // ---- P2: predicated u16 buffering, tree-prefix write indices ----
    unsigned short buf[BUFCAP];
    int c = 0;
    for (int i = 0; i < M_IND; i += 8) {
        int t[8];
#pragma unroll
        for (int u = 0; u < 8; u++) {
            float4 z = zs[i + u];
            t[u] = DIST(z) <= T0;
        }
        int s01 = t[0] + t[1], s23 = t[2] + t[3];
        int s45 = t[4] + t[5], s67 = t[6] + t[7];
        int s03 = s01 + s23;
        int pre[8];
        pre[0] = 0;         pre[1] = t[0];
        pre[2] = s01;       pre[3] = s01 + t[2];
        pre[4] = s03;       pre[5] = s03 + t[4];
        pre[6] = s03 + s45; pre[7] = s03 + s45 + t[6];
#pragma unroll
        for (int u = 0; u < 8; u++) {
            int w = c + pre[u];
            w = w < BUFCAP ? w : BUFCAP - 1;
            if (t[u]) buf[w] = (unsigned short)(i + u);
        }
        c += s03 + s45 + s67;
    }

    unsigned base = (unsigned)p * KNN;
    if (c <= BUFCAP) {
        // ---- P3: exact 16th among candidates (2-way interleaved bubble) ----
        float ks3[KNN];
#pragma unroll
        for (int s = 0; s < KNN; s++) ks3[s] = CUDART_INF_F;
        int c2 = c & ~1;
        for (int j = 0; j < c2; j += 2) {
            float4 za = zs[buf[j]], zb = zs[buf[j + 1]];
            float ta = DIST(za), tb = DIST(zb);
#pragma unroll
            for (int s = 0; s < KNN; s++) {
                float a = ks3[s];
                float m0 = fminf(a, ta);  ta = fmaxf(a, ta);
                float m1 = fminf(m0, tb); tb = fmaxf(m0, tb);
                ks3[s] = m1;
            }
        }
        if (c & 1) {
            float4 za = zs[buf[c - 1]];
            float ta = DIST(za);
#pragma unroll
            for (int s = 0; s < KNN; s++) {
                float a = ks3[s];
                ks3[s] = fminf(a, ta); ta = fmaxf(a, ta);
            }
        }
        float Tstar = ks3[KNN - 1];

        // ---- P4: predicated direct-STG emission (d<T*, then ties d==T*) ----
        int cnt = 0;
        for (int j = 0; j < c; j++) {
            int i = buf[j];
            float4 z = zs[i];
            float dd = DIST(z);
            bool em = (dd < Tstar) & (cnt < KNN);
            if (em) g_idx[base + cnt] = (unsigned)i;
            cnt += em;
        }
        for (int j = 0; j < c; j++) {
            int i = buf[j];
            float4 z = zs[i];
            float dd = DIST(z);
            bool em = (dd == Tstar) & (cnt < KNN);
            if (em) g_idx[base + cnt] = (unsigned)i;
            cnt += em;
        }
    } else {
        // Fallback: full exact u64 replace-max (pathological only)
        unsigned long long ks2[KNN];
#pragma unroll
        for (int s = 0; s < KNN; s++)
            ks2[s] = 0xFFFFFFFF00000000ull | (unsigned)s;
        unsigned long long kmax2 = 0xFFFFFFFF0000000Full;
        for (int i = 0; i < M_IND; i++) {
            float4 z = zs[i];
            float dd = DIST(z);
            unsigned long long key =
                ((unsigned long long)__float_as_uint(dd) << 32) | (unsigned)i;
            if (key < kmax2) {
#pragma unroll
                for (int s = 0; s < KNN; s++) ks2[s] = (ks2[s] == kmax2) ? key : ks2[s];
                unsigned long long m = ks2[0];
#pragma unroll
                for (int s = 1; s < KNN; s++) m = max(m, ks2[s]);
                kmax2 = m;
            }
        }
#pragma unroll
        for (int s = 0; s < KNN; s++)
            g_idx[base + s] = (unsigned)(ks2[s] & 0xFFFFFFFFu);
    }
#undef DIST
}

// ---------------------------------------------------------------------------
// Kernel 3: half-warp per point, register fp32 Gauss-Jordan; symmetric cov.
// ---------------------------------------------------------------------------
__global__ void solve_kernel(const float* __restrict__ X,
                             const float* __restrict__ Z,
                             const float* __restrict__ mu,
                             float* __restrict__ out, int N) {
    const unsigned FULL = 0xFFFFFFFFu;
    int lane = threadIdx.x & 31;
    int half = lane >> 4;
    int l = lane & 15;
    int p = (blockIdx.x << 4) + ((threadIdx.x >> 5) << 1) + half;
    int pc = p < N ? p : N - 1;

    float x0 = X[3 * pc], x1 = X[3 * pc + 1], x2 = X[3 * pc + 2];
    float xs = fmaf(x0, x0, fmaf(x1, x1, x2 * x2));

    unsigned idxv = g_idx[(size_t)pc * KNN + l];
    float zx = Z[3 * idxv], zy = Z[3 * idxv + 1], zz = Z[3 * idxv + 2];
    float z2 = fmaf(zx, zx, fmaf(zy, zy, zz * zz));
    float d2r = fmaxf(xs + z2 - 2.0f * fmaf(x0, zx, fmaf(x1, zy, x2 * zz)), 0.0f);
    float muv = mu[idxv];

    float a[17];
    a[16] = expf(-0.5f * d2r);   // rhs = lKxz

#pragma unroll
    for (int i = 0; i < 16; i++) {
        float zxi = __shfl_sync(FULL, zx, i, 16);
        float zyi = __shfl_sync(FULL, zy, i, 16);
        float zzi = __shfl_sync(FULL, zz, i, 16);
        float dx = zxi - zx, dy = zyi - zy, dz = zzi - zz;
        float d2 = fmaf(dx, dx, fmaf(dy, dy, dz * dz));
        a[i] = (i == l) ? (1.0f + 2e-4f) : expf(-0.5f * d2);
    }

#pragma unroll
    for (int k = 0; k < 16; k++) {
        float piv = __shfl_sync(FULL, a[k], k, 16);
        float rp = 1.0f / piv;
        float f = (l == k) ? 0.0f : a[k] * rp;
#pragma unroll
        for (int cc = k + 1; cc <= 16; cc++) {
            float bc = __shfl_sync(FULL, a[cc], k, 16);
            a[cc] = fmaf(-f, bc, a[cc]);
        }
    }
    float diag = a[0];
#pragma unroll
    for (int cc = 1; cc < 16; cc++) if (l == cc) diag = a[cc];
    float Wv = a[16] / diag;

    // cov = 1 + Wv^2 (su_ll - (1+1e-4)) + 2 * sum_{i<l} Wi Wv (su_il - kv_il)
    float acc = 0.0f;
#pragma unroll
    for (int i = 0; i < 15; i++) {
        float Wi = __shfl_sync(FULL, Wv, i, 16);
        unsigned ia = __shfl_sync(FULL, idxv, i, 16);
        float zxi = __shfl_sync(FULL, zx, i, 16);
        float zyi = __shfl_sync(FULL, zy, i, 16);
        float zzi = __shfl_sync(FULL, zz, i, 16);
        bool keep = (i < l);
        const float* addr = keep ? (g_Su + (size_t)ia * M_IND + idxv) : g_Su;
        float su = __ldg(addr);
        float dx = zxi - zx, dy = zyi - zy, dz = zzi - zz;
        float d2 = fmaf(dx, dx, fmaf(dy, dy, dz * dz));
        float kv = expf(-0.5f * d2);
        float coef = keep ? 2.0f * Wi * Wv : 0.0f;
        acc = fmaf(coef, su - kv, acc);
    }
    {
        float su_ll = __ldg(g_Su + (size_t)idxv * M_IND + idxv);
        acc = fmaf(Wv * Wv, su_ll - 1.0001f, acc);
    }
    float mpart = Wv * muv;
#pragma unroll
    for (int o = 8; o > 0; o >>= 1) {
        acc   += __shfl_xor_sync(FULL, acc, o, 16);
        mpart += __shfl_xor_sync(FULL, mpart, o, 16);
    }
    if (l == 0 && p < N) {
        out[p] = mpart;                                // mean
        float cov = 1.0f + acc;
        out[N + p] = sqrtf(fmaxf(cov, 0.05f));         // std
    }
}

// ---------------------------------------------------------------------------
extern "C" void kernel_launch(void* const* d_in, const int* in_sizes, int n_in,
                              void* d_out, int out_size) {
    const float* X      = (const float*)d_in[0];
    const float* Z      = (const float*)d_in[1];
    const float* Lu_raw = (const float*)d_in[2];
    const float* mu     = (const float*)d_in[3];
    float* out = (float*)d_out;
    int N = in_sizes[0] / 3;

    topk_kernel<<<(N + 127) / 128, 128>>>(X, Z, N);
    su_kernel<<<SU_BLOCKS, 256>>>(Lu_raw);
    solve_kernel<<<(N + 15) / 16, 256>>>(X, Z, mu, out, N);
}